// round 2
// baseline (speedup 1.0000x reference)
#include <cuda_runtime.h>
#include <math.h>

#define CH 64
#define HW 256
#define XS_STRIDE 68   // 64 cols + 4 pad (keeps 16B alignment, breaks bank alias)

// One CTA = one (batch, 8x8 block) location, all 64 channels.
// Pipeline in smem: load X -> DCT -> conv-as-GEMM over (in_ch, tap) -> IDCT -> store.
__global__ __launch_bounds__(256, 2)
void dct_conv_kernel(const float* __restrict__ x,
                     const float* __restrict__ cw,
                     const float* __restrict__ cb,
                     float* __restrict__ out)
{
    extern __shared__ float sm[];
    float* Xs = sm;                          // 64 x 68 : block pixels; reused as conv output
    float* Cs = Xs + CH * XS_STRIDE;         // 64 x 68 : DCT coefs, cols 64,65 zero-padded
    float* Ws = Cs + CH * XS_STRIDE;         // 64 x 192 : Ws[i*192 + o*3 + w]
    __shared__ float Ds[64];                 // 8x8 DCT matrix, row-major D[k*8+n]
    __shared__ float bs[64];

    const int tid  = threadIdx.x;
    const int bidx = blockIdx.x;
    const int bimg = bidx >> 10;             // batch (8)
    const int rem  = bidx & 1023;
    const int bh   = rem >> 5;               // block row (32)
    const int bw   = rem & 31;               // block col (32)

    // --- DCT matrix + bias ---
    if (tid < 64) {
        int k = tid >> 3, n = tid & 7;
        double v = sqrt(2.0 / 8.0) * cos(3.14159265358979323846 * (2 * n + 1) * k / 16.0);
        if (k == 0) v *= 0.70710678118654752440;
        Ds[tid] = (float)v;
        bs[tid] = cb[tid];
    }
    // --- zero-pad columns 64,65 of Cs (for the window-3 shift) ---
    if (tid < 128) {
        int c = tid >> 1;
        Cs[c * XS_STRIDE + 64 + (tid & 1)] = 0.f;
    }

    // --- load 64ch x 8x8 block of X (float4, full 32B sectors) ---
    const float* xb = x + ((size_t)bimg * CH) * (HW * HW) + (size_t)(bh * 8) * HW + bw * 8;
    #pragma unroll
    for (int k = 0; k < 4; k++) {
        int j = tid + k * 256;               // j in [0,1024)
        int c = j >> 4;
        int r = (j >> 1) & 7;
        int h = j & 1;
        float4 v = *(const float4*)(xb + (size_t)c * (HW * HW) + r * HW + h * 4);
        *(float4*)(Xs + c * XS_STRIDE + r * 8 + h * 4) = v;
    }

    // --- load conv weights, transposed to Ws[i*192 + o*3 + w] ---
    #pragma unroll
    for (int k = 0; k < 48; k++) {
        int idx = tid + k * 256;             // idx in [0,12288)
        int o = idx / 192;
        int r = idx - o * 192;
        int i = r / 3;
        int w = r - i * 3;
        Ws[i * 192 + o * 3 + w] = cw[idx];
    }
    __syncthreads();

    // --- forward DCT per channel: Cs[c] = D * Xblk * D^T (flat t = 8k+l) ---
    {
        int c = tid >> 2, q = tid & 3;
        #pragma unroll
        for (int kk = 0; kk < 2; kk++) {
            int k = q + 4 * kk;
            float tmp[8];
            #pragma unroll
            for (int m = 0; m < 8; m++) tmp[m] = 0.f;
            #pragma unroll
            for (int n = 0; n < 8; n++) {
                float d = Ds[k * 8 + n];
                #pragma unroll
                for (int m = 0; m < 8; m++)
                    tmp[m] += d * Xs[c * XS_STRIDE + n * 8 + m];
            }
            #pragma unroll
            for (int l = 0; l < 8; l++) {
                float acc = 0.f;
                #pragma unroll
                for (int m = 0; m < 8; m++)
                    acc += tmp[m] * Ds[l * 8 + m];
                Cs[c * XS_STRIDE + k * 8 + l] = acc;
            }
        }
    }
    __syncthreads();

    // --- conv as GEMM: O[o][t] = b[o] + sum_i sum_w Ws[i][o*3+w] * Cs[i][t+w] ---
    // Thread tile: 4 o x 4 t. Output aliases Xs (dead after DCT + barrier).
    {
        int og = tid >> 4;  int o0 = og * 4;
        int tg = tid & 15;  int t0 = tg * 4;
        float acc[4][4];
        #pragma unroll
        for (int oo = 0; oo < 4; oo++) {
            float bv = bs[o0 + oo];
            #pragma unroll
            for (int tt = 0; tt < 4; tt++) acc[oo][tt] = bv;
        }
        #pragma unroll 4
        for (int i = 0; i < CH; i++) {
            float4 c0 = *(const float4*)(Cs + i * XS_STRIDE + t0);
            float2 c1 = *(const float2*)(Cs + i * XS_STRIDE + t0 + 4);
            float cv[6] = {c0.x, c0.y, c0.z, c0.w, c1.x, c1.y};
            float4 w0 = *(const float4*)(Ws + i * 192 + o0 * 3);
            float4 w1 = *(const float4*)(Ws + i * 192 + o0 * 3 + 4);
            float4 w2 = *(const float4*)(Ws + i * 192 + o0 * 3 + 8);
            float wv[12] = {w0.x, w0.y, w0.z, w0.w,
                            w1.x, w1.y, w1.z, w1.w,
                            w2.x, w2.y, w2.z, w2.w};
            #pragma unroll
            for (int oo = 0; oo < 4; oo++) {
                #pragma unroll
                for (int w = 0; w < 3; w++) {
                    float wvv = wv[oo * 3 + w];
                    #pragma unroll
                    for (int tt = 0; tt < 4; tt++)
                        acc[oo][tt] += wvv * cv[tt + w];
                }
            }
        }
        float* Os = Xs;  // alias: safe, all Xs readers passed the barrier above
        #pragma unroll
        for (int oo = 0; oo < 4; oo++) {
            *(float4*)(Os + (o0 + oo) * XS_STRIDE + t0) =
                make_float4(acc[oo][0], acc[oo][1], acc[oo][2], acc[oo][3]);
        }
    }
    __syncthreads();

    // --- inverse DCT per channel: img = D^T * O * D, store direct to gmem ---
    {
        int c = tid >> 2, q = tid & 3;
        const float* Os = Xs;
        float* ob = out + ((size_t)bimg * CH + c) * (HW * HW) + (size_t)(bh * 8) * HW + bw * 8;
        #pragma unroll
        for (int nn = 0; nn < 2; nn++) {
            int n = q + 4 * nn;
            float tmp[8];
            #pragma unroll
            for (int l = 0; l < 8; l++) tmp[l] = 0.f;
            #pragma unroll
            for (int k = 0; k < 8; k++) {
                float d = Ds[k * 8 + n];
                #pragma unroll
                for (int l = 0; l < 8; l++)
                    tmp[l] += d * Os[c * XS_STRIDE + k * 8 + l];
            }
            float res[8];
            #pragma unroll
            for (int m = 0; m < 8; m++) {
                float acc = 0.f;
                #pragma unroll
                for (int l = 0; l < 8; l++)
                    acc += tmp[l] * Ds[l * 8 + m];
                res[m] = acc;
            }
            *(float4*)(ob + n * HW)     = make_float4(res[0], res[1], res[2], res[3]);
            *(float4*)(ob + n * HW + 4) = make_float4(res[4], res[5], res[6], res[7]);
        }
    }
}

extern "C" void kernel_launch(void* const* d_in, const int* in_sizes, int n_in,
                              void* d_out, int out_size)
{
    (void)in_sizes; (void)n_in; (void)out_size;
    const float* x  = (const float*)d_in[0];
    const float* cw = (const float*)d_in[1];
    const float* cb = (const float*)d_in[2];
    float* out = (float*)d_out;

    size_t smem = (size_t)(2 * CH * XS_STRIDE + CH * 192) * sizeof(float);  // 83968 B
    cudaFuncSetAttribute(dct_conv_kernel,
                         cudaFuncAttributeMaxDynamicSharedMemorySize, (int)smem);
    dct_conv_kernel<<<8192, 256, smem>>>(x, cw, cb, out);
}

// round 7
// speedup vs baseline: 1.6225x; 1.6225x over previous
#include <cuda_runtime.h>

#define G 8              // image blocks per CTA (horizontal)
#define BLKW 68          // per-block width in Cs: 64 data + 2 zeros + 2 pad (16B-aligned groups)
#define ROWS (G * BLKW)  // 544 floats per channel row in Cs
#define WST 68           // Ws row stride (192 rows of 64 + pad; 16B aligned)
#define NTHREADS 512

typedef unsigned long long ull;

// 8x8 DCT-II matrix (orthonormal), full fp32 precision, compile-time constants.
// __device__ constexpr: usable in device code without --expt-relaxed-constexpr;
// constant indices fold to FFMA immediates (rt_SMSP=1 imm path), no LDC/smem.
static __device__ constexpr float DM[8][8] = {
  { 0.35355339059327373f, 0.35355339059327373f, 0.35355339059327373f, 0.35355339059327373f,
    0.35355339059327373f, 0.35355339059327373f, 0.35355339059327373f, 0.35355339059327373f },
  { 0.49039264020161522f, 0.41573480615127262f, 0.27778511650980114f, 0.09754516100806417f,
   -0.09754516100806417f,-0.27778511650980114f,-0.41573480615127262f,-0.49039264020161522f },
  { 0.46193976625564337f, 0.19134171618254492f,-0.19134171618254492f,-0.46193976625564337f,
   -0.46193976625564337f,-0.19134171618254492f, 0.19134171618254492f, 0.46193976625564337f },
  { 0.41573480615127262f,-0.09754516100806417f,-0.49039264020161522f,-0.27778511650980114f,
    0.27778511650980114f, 0.49039264020161522f, 0.09754516100806417f,-0.41573480615127262f },
  { 0.35355339059327373f,-0.35355339059327373f,-0.35355339059327373f, 0.35355339059327373f,
    0.35355339059327373f,-0.35355339059327373f,-0.35355339059327373f, 0.35355339059327373f },
  { 0.27778511650980114f,-0.49039264020161522f, 0.09754516100806417f, 0.41573480615127262f,
   -0.41573480615127262f,-0.09754516100806417f, 0.49039264020161522f,-0.27778511650980114f },
  { 0.19134171618254492f,-0.46193976625564337f, 0.46193976625564337f,-0.19134171618254492f,
   -0.19134171618254492f, 0.46193976625564337f,-0.46193976625564337f, 0.19134171618254492f },
  { 0.09754516100806417f,-0.27778511650980114f, 0.41573480615127262f,-0.49039264020161522f,
    0.49039264020161522f,-0.41573480615127262f, 0.27778511650980114f,-0.09754516100806417f }
};

static __device__ __forceinline__ ull ffma2(ull a, ull b, ull c) {
    ull d;
    asm("fma.rn.f32x2 %0, %1, %2, %3;" : "=l"(d) : "l"(a), "l"(b), "l"(c));
    return d;
}
static __device__ __forceinline__ ull dup2(float v) {
    ull d;
    asm("mov.b64 %0, {%1, %1};" : "=l"(d) : "f"(v));
    return d;
}
static __device__ __forceinline__ void unpack2(ull v, float& lo, float& hi) {
    asm("mov.b64 {%0, %1}, %2;" : "=f"(lo), "=f"(hi) : "l"(v));
}
static __device__ __forceinline__ ull d2l(double v) { return __double_as_longlong(v); }

__global__ __launch_bounds__(NTHREADS, 1)
void dct_conv_kernel(const float* __restrict__ x,
                     const float* __restrict__ cw,
                     const float* __restrict__ cb,
                     float* __restrict__ out)
{
    extern __shared__ float sm[];
    float* Cs = sm;                      // 64 x 544 : X pixels -> DCT coefs -> conv output
    float* Ws = Cs + 64 * ROWS;          // 192 x 68 : Ws[(i*3+w)*WST + o]
    __shared__ alignas(16) float bs[64];

    const int tid  = threadIdx.x;
    const int bidx = blockIdx.x;
    const int bimg = bidx >> 7;          // batch (8)
    const int rem  = bidx & 127;
    const int bh   = rem >> 2;           // block row (32)
    const int bwg  = rem & 3;            // group of 8 horizontal blocks (4)

    // ---------------- phase 1: fill smem ----------------
    if (tid < 64) bs[tid] = cb[tid];

    // zeros at cols 64..67 of every (i, g) segment
    {
        int i = tid >> 3, g = tid & 7;
        *(float4*)(Cs + i * ROWS + g * BLKW + 64) = make_float4(0.f, 0.f, 0.f, 0.f);
    }

    // X pixels: CTA covers 64 channels x 8 rows x 64 cols
    const float* xb = x + ((size_t)bimg * 64) * 65536 + (size_t)(bh * 8) * 256 + bwg * 64;
    #pragma unroll
    for (int k = 0; k < 16; k++) {
        int j  = tid + k * NTHREADS;     // [0, 8192) float4s
        int c  = j >> 7;                 // 128 float4 per channel
        int j2 = j & 127;
        int r  = j2 >> 4;                // row 0..7
        int q  = j2 & 15;                // float4 within 64-col span
        float4 v = *(const float4*)(xb + (size_t)c * 65536 + r * 256 + q * 4);
        int g = q >> 1, h = q & 1;
        *(float4*)(Cs + c * ROWS + g * BLKW + r * 8 + h * 4) = v;
    }

    // weights transposed: Ws[(i*3+w)*WST + o] = cw[o*192 + i*3 + w]
    #pragma unroll
    for (int k = 0; k < 24; k++) {
        int idx = tid + k * NTHREADS;    // [0, 12288)
        int o = idx / 192;
        int r = idx - o * 192;
        Ws[r * WST + o] = cw[idx];
    }
    __syncthreads();

    // ---------------- phase 2: forward DCT (registers, immediate D) ----------------
    {
        const int c = tid >> 3, g = tid & 7;
        float* cp = Cs + c * ROWS + g * BLKW;
        float X[8][8];
        #pragma unroll
        for (int r = 0; r < 8; r++) {
            float4 a = *(const float4*)(cp + r * 8);
            float4 b = *(const float4*)(cp + r * 8 + 4);
            X[r][0] = a.x; X[r][1] = a.y; X[r][2] = a.z; X[r][3] = a.w;
            X[r][4] = b.x; X[r][5] = b.y; X[r][6] = b.z; X[r][7] = b.w;
        }
        // stage 1: Y[n][l] = sum_m X[n][m] * DM[l][m]
        #pragma unroll
        for (int n = 0; n < 8; n++) {
            float t[8];
            #pragma unroll
            for (int l = 0; l < 8; l++) {
                float s = X[n][0] * DM[l][0];
                #pragma unroll
                for (int m = 1; m < 8; m++) s = fmaf(X[n][m], DM[l][m], s);
                t[l] = s;
            }
            #pragma unroll
            for (int l = 0; l < 8; l++) X[n][l] = t[l];
        }
        // stage 2: C[k][l] = sum_n DM[k][n] * Y[n][l]; write back in place
        #pragma unroll
        for (int k = 0; k < 8; k++) {
            float t[8];
            #pragma unroll
            for (int l = 0; l < 8; l++) {
                float s = DM[k][0] * X[0][l];
                #pragma unroll
                for (int n = 1; n < 8; n++) s = fmaf(DM[k][n], X[n][l], s);
                t[l] = s;
            }
            *(float4*)(cp + k * 8)     = make_float4(t[0], t[1], t[2], t[3]);
            *(float4*)(cp + k * 8 + 4) = make_float4(t[4], t[5], t[6], t[7]);
        }
    }
    __syncthreads();

    // ---------------- phase 3: conv as GEMM via FFMA2 ----------------
    // O[o][t] = b[o] + sum_i sum_w W[o,i,w] * C[i][t+w], T = 512 (8 blocks x 64)
    {
        const int og = tid >> 6;         // 8 groups of 8 output channels (warp-uniform)
        const int o0 = og * 8;
        const int tg = tid & 63;
        const int cg = tg >> 3;          // block
        const int tb = (tg & 7) * 8;     // t within block
        const float* crow0 = Cs + cg * BLKW + tb;

        ull acc[4][8];
        {
            double2 b0 = *(const double2*)(bs + o0);
            double2 b1 = *(const double2*)(bs + o0 + 4);
            ull bp[4] = { d2l(b0.x), d2l(b0.y), d2l(b1.x), d2l(b1.y) };
            #pragma unroll
            for (int p = 0; p < 4; p++)
                #pragma unroll
                for (int t = 0; t < 8; t++) acc[p][t] = bp[p];
        }

        #pragma unroll 2
        for (int i = 0; i < 64; i++) {
            const float* cr = crow0 + i * ROWS;
            float4 ca = *(const float4*)(cr);
            float4 cb4 = *(const float4*)(cr + 4);
            float4 cc = *(const float4*)(cr + 8);
            float cv[12] = { ca.x, ca.y, ca.z, ca.w,
                             cb4.x, cb4.y, cb4.z, cb4.w,
                             cc.x, cc.y, cc.z, cc.w };
            const float* wr = Ws + (i * 3) * WST + o0;   // warp-uniform address
            double2 wA0 = *(const double2*)(wr);
            double2 wA1 = *(const double2*)(wr + 4);
            double2 wB0 = *(const double2*)(wr + WST);
            double2 wB1 = *(const double2*)(wr + WST + 4);
            double2 wC0 = *(const double2*)(wr + 2 * WST);
            double2 wC1 = *(const double2*)(wr + 2 * WST + 4);
            ull w0p[4] = { d2l(wA0.x), d2l(wA0.y), d2l(wA1.x), d2l(wA1.y) };
            ull w1p[4] = { d2l(wB0.x), d2l(wB0.y), d2l(wB1.x), d2l(wB1.y) };
            ull w2p[4] = { d2l(wC0.x), d2l(wC0.y), d2l(wC1.x), d2l(wC1.y) };

            ull dd0 = dup2(cv[0]);
            ull dd1 = dup2(cv[1]);
            ull dd2 = dup2(cv[2]);
            #pragma unroll
            for (int t = 0; t < 8; t++) {
                #pragma unroll
                for (int p = 0; p < 4; p++) {
                    acc[p][t] = ffma2(w0p[p], dd0, acc[p][t]);
                    acc[p][t] = ffma2(w1p[p], dd1, acc[p][t]);
                    acc[p][t] = ffma2(w2p[p], dd2, acc[p][t]);
                }
                dd0 = dd1; dd1 = dd2;
                if (t < 7) dd2 = dup2(cv[t + 3]);
            }
        }

        __syncthreads();   // all Cs reads done before overwriting with O

        float* orow = Cs + cg * BLKW + tb;
        #pragma unroll
        for (int p = 0; p < 4; p++) {
            float lo[8], hi[8];
            #pragma unroll
            for (int t = 0; t < 8; t++) unpack2(acc[p][t], lo[t], hi[t]);
            float* r0 = orow + (size_t)(o0 + 2 * p) * ROWS;
            float* r1 = orow + (size_t)(o0 + 2 * p + 1) * ROWS;
            *(float4*)(r0)     = make_float4(lo[0], lo[1], lo[2], lo[3]);
            *(float4*)(r0 + 4) = make_float4(lo[4], lo[5], lo[6], lo[7]);
            *(float4*)(r1)     = make_float4(hi[0], hi[1], hi[2], hi[3]);
            *(float4*)(r1 + 4) = make_float4(hi[4], hi[5], hi[6], hi[7]);
        }
    }
    __syncthreads();

    // ---------------- phase 4: inverse DCT (registers, immediate D) -> gmem ----------------
    {
        const int o = tid >> 3, g = tid & 7;
        const float* op = Cs + o * ROWS + g * BLKW;
        float Y[8][8];
        #pragma unroll
        for (int k = 0; k < 8; k++) {
            float4 a = *(const float4*)(op + k * 8);
            float4 b = *(const float4*)(op + k * 8 + 4);
            Y[k][0] = a.x; Y[k][1] = a.y; Y[k][2] = a.z; Y[k][3] = a.w;
            Y[k][4] = b.x; Y[k][5] = b.y; Y[k][6] = b.z; Y[k][7] = b.w;
        }
        // stage 1: P[k][m] = sum_l Y[k][l] * DM[l][m]
        #pragma unroll
        for (int k = 0; k < 8; k++) {
            float t[8];
            #pragma unroll
            for (int m = 0; m < 8; m++) {
                float s = Y[k][0] * DM[0][m];
                #pragma unroll
                for (int l = 1; l < 8; l++) s = fmaf(Y[k][l], DM[l][m], s);
                t[m] = s;
            }
            #pragma unroll
            for (int m = 0; m < 8; m++) Y[k][m] = t[m];
        }
        // stage 2: img[n][m] = sum_k DM[k][n] * P[k][m]; store
        float* ob = out + ((size_t)bimg * 64 + o) * 65536 + (size_t)(bh * 8) * 256 + bwg * 64 + g * 8;
        #pragma unroll
        for (int n = 0; n < 8; n++) {
            float t[8];
            #pragma unroll
            for (int m = 0; m < 8; m++) {
                float s = DM[0][n] * Y[0][m];
                #pragma unroll
                for (int k = 1; k < 8; k++) s = fmaf(DM[k][n], Y[k][m], s);
                t[m] = s;
            }
            *(float4*)(ob + n * 256)     = make_float4(t[0], t[1], t[2], t[3]);
            *(float4*)(ob + n * 256 + 4) = make_float4(t[4], t[5], t[6], t[7]);
        }
    }
}

extern "C" void kernel_launch(void* const* d_in, const int* in_sizes, int n_in,
                              void* d_out, int out_size)
{
    (void)in_sizes; (void)n_in; (void)out_size;
    const float* x  = (const float*)d_in[0];
    const float* cw = (const float*)d_in[1];
    const float* cb = (const float*)d_in[2];
    float* out = (float*)d_out;

    size_t smem = (size_t)(64 * ROWS + 192 * WST) * sizeof(float);  // 191488 B
    cudaFuncSetAttribute(dct_conv_kernel,
                         cudaFuncAttributeMaxDynamicSharedMemorySize, (int)smem);
    dct_conv_kernel<<<1024, NTHREADS, smem>>>(x, cw, cb, out);
}

// round 16
// speedup vs baseline: 3.2147x; 1.9813x over previous
#include <cuda_runtime.h>
#include <cstdint>

#define NT 512
// ---- tc-path smem layout (no-swizzle canonical core-matrix layout) ----
#define A_PANEL 8240u                      // 515 rows * 16B (512 data + 2 zero + 1 pad)
#define A_LBO   515u
#define SMEM_A  0u
#define A_BYTES (16u * A_PANEL)            // 131840
#define SMEM_W  A_BYTES                    // 16B-aligned
#define W_TAP   16384u                     // 16 panels * 1024B
#define W_LBO   64u
#define OUT_STRIDE 544
#define IDESC_TF32 ((1u<<4)|(2u<<7)|(2u<<10)|((64u/8u)<<17)|((128u/16u)<<24))
// ---- fallback (FFMA2) smem layout ----
#define G 8
#define BLKW 68
#define ROWS (G * BLKW)                    // 544
#define WST 68
#define SMEM_LAUNCH 191488

typedef unsigned long long ull;

static __device__ constexpr float DM[8][8] = {
  { 0.35355339059327373f, 0.35355339059327373f, 0.35355339059327373f, 0.35355339059327373f,
    0.35355339059327373f, 0.35355339059327373f, 0.35355339059327373f, 0.35355339059327373f },
  { 0.49039264020161522f, 0.41573480615127262f, 0.27778511650980114f, 0.09754516100806417f,
   -0.09754516100806417f,-0.27778511650980114f,-0.41573480615127262f,-0.49039264020161522f },
  { 0.46193976625564337f, 0.19134171618254492f,-0.19134171618254492f,-0.46193976625564337f,
   -0.46193976625564337f,-0.19134171618254492f, 0.19134171618254492f, 0.46193976625564337f },
  { 0.41573480615127262f,-0.09754516100806417f,-0.49039264020161522f,-0.27778511650980114f,
    0.27778511650980114f, 0.49039264020161522f, 0.09754516100806417f,-0.41573480615127262f },
  { 0.35355339059327373f,-0.35355339059327373f,-0.35355339059327373f, 0.35355339059327373f,
    0.35355339059327373f,-0.35355339059327373f,-0.35355339059327373f, 0.35355339059327373f },
  { 0.27778511650980114f,-0.49039264020161522f, 0.09754516100806417f, 0.41573480615127262f,
   -0.41573480615127262f,-0.09754516100806417f, 0.49039264020161522f,-0.27778511650980114f },
  { 0.19134171618254492f,-0.46193976625564337f, 0.46193976625564337f,-0.19134171618254492f,
   -0.19134171618254492f, 0.46193976625564337f,-0.46193976625564337f, 0.19134171618254492f },
  { 0.09754516100806417f,-0.27778511650980114f, 0.41573480615127262f,-0.49039264020161522f,
    0.49039264020161522f,-0.41573480615127262f, 0.27778511650980114f,-0.09754516100806417f }
};

static __device__ __forceinline__ unsigned smem_u32(const void* p) {
    unsigned a;
    asm("{ .reg .u64 t; cvta.to.shared.u64 t, %1; cvt.u32.u64 %0, t; }" : "=r"(a) : "l"(p));
    return a;
}
static __device__ __forceinline__ ull ffma2(ull a, ull b, ull c) {
    ull d;
    asm("fma.rn.f32x2 %0, %1, %2, %3;" : "=l"(d) : "l"(a), "l"(b), "l"(c));
    return d;
}
static __device__ __forceinline__ ull dup2(float v) {
    ull d;
    asm("mov.b64 %0, {%1, %1};" : "=l"(d) : "f"(v));
    return d;
}
static __device__ __forceinline__ void unpack2(ull v, float& lo, float& hi) {
    asm("mov.b64 {%0, %1}, %2;" : "=f"(lo), "=f"(hi) : "l"(v));
}
static __device__ __forceinline__ ull d2l(double v) { return __double_as_longlong(v); }

#if defined(__CUDA_ARCH_FEAT_SM103_ALL) || defined(__CUDA_ARCH_FEAT_SM100_ALL) || !defined(__CUDA_ARCH__)
#define HAS_TCGEN05 1
#else
#define HAS_TCGEN05 0
#endif

#if HAS_TCGEN05
static __device__ __forceinline__ unsigned tf32_bits(float v) {
    unsigned u;
    asm("cvt.rna.tf32.f32 %0, %1;" : "=r"(u) : "f"(v));
    return u;
}
static __device__ __forceinline__ unsigned elect_one() {
    unsigned p;
    asm volatile("{ .reg .pred p; elect.sync _|p, 0xFFFFFFFF; selp.b32 %0, 1, 0, p; }" : "=r"(p));
    return p;
}
// No-swizzle (layout_type=0) descriptor: version=1, SBO=8 (contiguous 8-row groups)
static __device__ __forceinline__ uint64_t desc_ns(unsigned addr, unsigned lbo) {
    return (uint64_t(1) << 46) | (uint64_t(8) << 32) |
           ((uint64_t)lbo << 16) | ((uint64_t)(addr >> 4) & 0x3FFF);
}
static __device__ __forceinline__ void mma_tf32_ss(unsigned d, uint64_t ad, uint64_t bd,
                                                   unsigned idesc, unsigned en) {
    asm volatile(
        "{\n\t.reg .pred p;\n\tsetp.ne.u32 p, %4, 0;\n\t"
        "tcgen05.mma.cta_group::1.kind::tf32 [%0], %1, %2, %3, {%5, %5, %5, %5}, p;\n\t}"
        :: "r"(d), "l"(ad), "l"(bd), "r"(idesc), "r"(en), "r"(0u) : "memory");
}
static __device__ __forceinline__ void tmem_ld32(unsigned* r, unsigned a) {
    asm volatile(
        "tcgen05.ld.sync.aligned.32x32b.x32.b32 "
        "{%0,%1,%2,%3,%4,%5,%6,%7,%8,%9,%10,%11,%12,%13,%14,%15,"
        "%16,%17,%18,%19,%20,%21,%22,%23,%24,%25,%26,%27,%28,%29,%30,%31}, [%32];"
        : "=r"(r[0]),"=r"(r[1]),"=r"(r[2]),"=r"(r[3]),"=r"(r[4]),"=r"(r[5]),"=r"(r[6]),"=r"(r[7]),
          "=r"(r[8]),"=r"(r[9]),"=r"(r[10]),"=r"(r[11]),"=r"(r[12]),"=r"(r[13]),"=r"(r[14]),"=r"(r[15]),
          "=r"(r[16]),"=r"(r[17]),"=r"(r[18]),"=r"(r[19]),"=r"(r[20]),"=r"(r[21]),"=r"(r[22]),"=r"(r[23]),
          "=r"(r[24]),"=r"(r[25]),"=r"(r[26]),"=r"(r[27]),"=r"(r[28]),"=r"(r[29]),"=r"(r[30]),"=r"(r[31])
        : "r"(a));
}
#endif

__global__ __launch_bounds__(NT, 1)
void dct_tc_kernel(const float* __restrict__ x,
                   const float* __restrict__ cw,
                   const float* __restrict__ cb,
                   float* __restrict__ out)
{
#if HAS_TCGEN05
    // ================= tensor-core path (sm_103a) =================
    extern __shared__ char smem[];
    __shared__ unsigned tmem_ptr_s;
    __shared__ ull      mbar_s;
    __shared__ alignas(16) float bs[64];
    __shared__ float fix62[512];
    __shared__ float fix63[512];

    const int tid = threadIdx.x;
    const int wid = tid >> 5;
    const int bidx = blockIdx.x;
    const int bimg = bidx >> 7;
    const int rem  = bidx & 127;
    const int bh   = rem >> 2;
    const int bwg  = rem & 3;

    const unsigned sb = smem_u32(smem);

    if (wid == 0) {
        unsigned dst = smem_u32(&tmem_ptr_s);
        asm volatile("tcgen05.alloc.cta_group::1.sync.aligned.shared::cta.b32 [%0], 256;"
                     :: "r"(dst) : "memory");
        asm volatile("tcgen05.relinquish_alloc_permit.cta_group::1.sync.aligned;");
    }
    if (tid == 0) {
        unsigned mb = smem_u32(&mbar_s);
        asm volatile("mbarrier.init.shared.b64 [%0], 1;" :: "r"(mb) : "memory");
    }
    if (tid < 64) bs[tid] = cb[tid];

    // zero A tail rows 512,513 (tap overreach) + pad row 514, all 16 panels
    if (tid < 48) {
        unsigned panel = (unsigned)tid >> 1 & 15u;
        unsigned half  = (unsigned)tid & 1u;
        unsigned rowb  = (tid < 32) ? (512u + half) : 514u;
        if (tid >= 32) panel = (unsigned)(tid - 32);
        *(float4*)(smem + SMEM_A + panel * A_PANEL + rowb * 16u) =
            make_float4(0.f, 0.f, 0.f, 0.f);
    }

    // W fill: tf32, per-tap region, linear core-matrix layout:
    // addr = tap*W_TAP + (i/4)*1024 + o*16 + (i%4)*4
    #pragma unroll
    for (int k = 0; k < 24; k++) {
        int idx = tid + k * NT;              // [0, 12288)
        int o = idx / 192;
        int r = idx - o * 192;
        int i = r / 3;
        int w = r - i * 3;
        unsigned off = (unsigned)w * W_TAP + (unsigned)(i >> 2) * 1024u +
                       (unsigned)o * 16u + (unsigned)(i & 3) * 4u;
        *(unsigned*)(smem + SMEM_W + off) = tf32_bits(cw[idx]);
    }

    // DCT: X -> regs -> Ct (tf32) in A region, addr(r,c) = (c/4)*A_PANEL + r*16 + (c%4)*4
    {
        const int c = tid & 63, g = tid >> 6;
        const float* xb = x + ((size_t)(bimg * 64 + c)) * 65536 +
                          (size_t)(bh * 8) * 256 + bwg * 64 + g * 8;
        float X[8][8];
        #pragma unroll
        for (int r = 0; r < 8; r++) {
            float4 a = *(const float4*)(xb + r * 256);
            float4 b = *(const float4*)(xb + r * 256 + 4);
            X[r][0] = a.x; X[r][1] = a.y; X[r][2] = a.z; X[r][3] = a.w;
            X[r][4] = b.x; X[r][5] = b.y; X[r][6] = b.z; X[r][7] = b.w;
        }
        #pragma unroll
        for (int n = 0; n < 8; n++) {
            float t[8];
            #pragma unroll
            for (int l = 0; l < 8; l++) {
                float s = X[n][0] * DM[l][0];
                #pragma unroll
                for (int m = 1; m < 8; m++) s = fmaf(X[n][m], DM[l][m], s);
                t[l] = s;
            }
            #pragma unroll
            for (int l = 0; l < 8; l++) X[n][l] = t[l];
        }
        const unsigned colb = (unsigned)(c >> 2) * A_PANEL + (unsigned)(c & 3) * 4u;
        #pragma unroll
        for (int k = 0; k < 8; k++) {
            float t[8];
            #pragma unroll
            for (int l = 0; l < 8; l++) {
                float s = DM[k][0] * X[0][l];
                #pragma unroll
                for (int n = 1; n < 8; n++) s = fmaf(DM[k][n], X[n][l], s);
                t[l] = s;
            }
            #pragma unroll
            for (int l = 0; l < 8; l++) {
                unsigned row = (unsigned)(g * 64 + k * 8 + l);
                *(unsigned*)(smem + SMEM_A + colb + row * 16u) = tf32_bits(t[l]);
            }
        }
    }
    __syncthreads();

    // MMA: 4 M-tiles x 3 taps x 8 ksteps, accumulate in TMEM.
    // Linear layout: tap shift = +w units (w rows * 16B); tile = +128 units;
    // K-step = 2 panels: A +1030 units, W +128 units.
    const unsigned tb = tmem_ptr_s;
    if (wid == 0) {
        asm volatile("fence.proxy.async.shared::cta;" ::: "memory");
        if (elect_one()) {
            const uint64_t a_base = desc_ns(sb + SMEM_A, A_LBO);
            #pragma unroll
            for (int tile = 0; tile < 4; tile++) {
                unsigned d = tb + tile * 64;
                #pragma unroll
                for (int w = 0; w < 3; w++) {
                    uint64_t ad0 = a_base + (uint64_t)(tile * 128 + w);
                    uint64_t bd0 = desc_ns(sb + SMEM_W + (unsigned)w * W_TAP, W_LBO);
                    #pragma unroll
                    for (int ks = 0; ks < 8; ks++) {
                        uint64_t ad = ad0 + (uint64_t)(ks * 1030);
                        uint64_t bd = bd0 + (uint64_t)(ks * 128);
                        mma_tf32_ss(d, ad, bd, IDESC_TF32, (w | ks) ? 1u : 0u);
                    }
                }
            }
            unsigned mb = smem_u32(&mbar_s);
            asm volatile(
                "tcgen05.commit.cta_group::1.mbarrier::arrive::one.shared::cluster.b64 [%0];"
                :: "r"(mb) : "memory");
        }
    }

    // Fixup GEMVs (overlap MMA): boundary contamination at t_in 62/63
    if (tid < 448) {
        const int b = tid >> 6, o = tid & 63;
        const unsigned r0 = (unsigned)((b + 1) * 64);
        float acc1 = 0.f, acc2a = 0.f, acc2b = 0.f;
        #pragma unroll 4
        for (int i = 0; i < 64; i += 4) {
            unsigned ap = (unsigned)(i >> 2) * A_PANEL;
            unsigned wp = (unsigned)(i >> 2) * 1024u + (unsigned)o * 16u;
            float4 a0 = *(const float4*)(smem + SMEM_A + ap + r0 * 16u);
            float4 a1 = *(const float4*)(smem + SMEM_A + ap + (r0 + 1) * 16u);
            float4 w1 = *(const float4*)(smem + SMEM_W + 1u * W_TAP + wp);
            float4 w2 = *(const float4*)(smem + SMEM_W + 2u * W_TAP + wp);
            acc1  = fmaf(w1.x, a0.x, fmaf(w1.y, a0.y, fmaf(w1.z, a0.z, fmaf(w1.w, a0.w, acc1))));
            acc2a = fmaf(w2.x, a0.x, fmaf(w2.y, a0.y, fmaf(w2.z, a0.z, fmaf(w2.w, a0.w, acc2a))));
            acc2b = fmaf(w2.x, a1.x, fmaf(w2.y, a1.y, fmaf(w2.z, a1.z, fmaf(w2.w, a1.w, acc2b))));
        }
        fix62[b * 64 + o] = acc2a;
        fix63[b * 64 + o] = acc1 + acc2b;
    } else {
        fix62[448 + (tid & 63)] = 0.f;   // block 7 taps hit zeroed tail rows
        fix63[448 + (tid & 63)] = 0.f;
    }
    __syncthreads();

    // wait MMA, TMEM->regs, bias/fixup, transpose-store [o][t]
    {
        unsigned mb = smem_u32(&mbar_s);
        unsigned done;
        asm volatile(
            "{\n\t.reg .pred p;\n\t"
            "mbarrier.try_wait.parity.acquire.cta.shared::cta.b64 p, [%1], 0;\n\t"
            "selp.b32 %0, 1, 0, p;\n\t}"
            : "=r"(done) : "r"(mb) : "memory");
        if (!done) {
            asm volatile(
                "{\n\t.reg .pred P1;\n\t"
                "WL_%=:\n\t"
                "mbarrier.try_wait.parity.acquire.cta.shared::cta.b64 P1, [%0], 0, 0x989680;\n\t"
                "@P1 bra.uni WD_%=;\n\t"
                "bra.uni WL_%=;\n\t"
                "WD_%=:\n\t}"
                :: "r"(mb) : "memory");
        }
        asm volatile("tcgen05.fence::after_thread_sync;" ::: "memory");

        const int wg = tid >> 7, wg_tid = tid & 127;
        unsigned d[64];
        tmem_ld32(d,      tb + wg * 64);
        tmem_ld32(d + 32, tb + wg * 64 + 32);
        asm volatile("tcgen05.wait::ld.sync.aligned;" ::: "memory");

        const int t = wg * 128 + wg_tid;
        const int g = t >> 6, t_in = t & 63;
        float* orow = (float*)(smem) + g * 68 + t_in;
        if (t_in == 62) {
            #pragma unroll
            for (int o = 0; o < 64; o++)
                orow[o * OUT_STRIDE] = __uint_as_float(d[o]) + bs[o] - fix62[g * 64 + o];
        } else if (t_in == 63) {
            #pragma unroll
            for (int o = 0; o < 64; o++)
                orow[o * OUT_STRIDE] = __uint_as_float(d[o]) + bs[o] - fix63[g * 64 + o];
        } else {
            #pragma unroll
            for (int o = 0; o < 64; o++)
                orow[o * OUT_STRIDE] = __uint_as_float(d[o]) + bs[o];
        }
    }
    __syncthreads();

    // inverse DCT -> gmem
    {
        const int o = tid >> 3, g = tid & 7;
        const float* op = (const float*)(smem) + o * OUT_STRIDE + g * 68;
        float Y[8][8];
        #pragma unroll
        for (int k = 0; k < 8; k++)
            #pragma unroll
            for (int l = 0; l < 8; l++) Y[k][l] = op[k * 8 + l];
        #pragma unroll
        for (int k = 0; k < 8; k++) {
            float t[8];
            #pragma unroll
            for (int m = 0; m < 8; m++) {
                float s = Y[k][0] * DM[0][m];
                #pragma unroll
                for (int l = 1; l < 8; l++) s = fmaf(Y[k][l], DM[l][m], s);
                t[m] = s;
            }
            #pragma unroll
            for (int m = 0; m < 8; m++) Y[k][m] = t[m];
        }
        float* ob = out + ((size_t)(bimg * 64 + o)) * 65536 +
                    (size_t)(bh * 8) * 256 + bwg * 64 + g * 8;
        #pragma unroll
        for (int n = 0; n < 8; n++) {
            float t[8];
            #pragma unroll
            for (int m = 0; m < 8; m++) {
                float s = DM[0][n] * Y[0][m];
                #pragma unroll
                for (int k = 1; k < 8; k++) s = fmaf(DM[k][n], Y[k][m], s);
                t[m] = s;
            }
            *(float4*)(ob + n * 256)     = make_float4(t[0], t[1], t[2], t[3]);
            *(float4*)(ob + n * 256 + 4) = make_float4(t[4], t[5], t[6], t[7]);
        }
    }
    __syncthreads();
    if (wid == 0) {
        asm volatile("tcgen05.dealloc.cta_group::1.sync.aligned.b32 %0, 256;" :: "r"(tb));
    }

#else
    // ============ fallback: proven FFMA2 path (compiles on plain sm_103) ============
    extern __shared__ float smf[];
    float* Cs = smf;                      // 64 x 544
    float* Ws = Cs + 64 * ROWS;           // 192 x 68
    __shared__ alignas(16) float bs[64];

    const int tid  = threadIdx.x;
    const int bidx = blockIdx.x;
    const int bimg = bidx >> 7;
    const int rem  = bidx & 127;
    const int bh   = rem >> 2;
    const int bwg  = rem & 3;

    if (tid < 64) bs[tid] = cb[tid];
    {
        int i = tid >> 3, g = tid & 7;
        *(float4*)(Cs + i * ROWS + g * BLKW + 64) = make_float4(0.f, 0.f, 0.f, 0.f);
    }
    const float* xb = x + ((size_t)bimg * 64) * 65536 + (size_t)(bh * 8) * 256 + bwg * 64;
    #pragma unroll
    for (int k = 0; k < 16; k++) {
        int j  = tid + k * NT;
        int c  = j >> 7;
        int j2 = j & 127;
        int r  = j2 >> 4;
        int q  = j2 & 15;
        float4 v = *(const float4*)(xb + (size_t)c * 65536 + r * 256 + q * 4);
        int g = q >> 1, h = q & 1;
        *(float4*)(Cs + c * ROWS + g * BLKW + r * 8 + h * 4) = v;
    }
    #pragma unroll
    for (int k = 0; k < 24; k++) {
        int idx = tid + k * NT;
        int o = idx / 192;
        int r = idx - o * 192;
        Ws[r * WST + o] = cw[idx];
    }
    __syncthreads();

    {
        const int c = tid >> 3, g = tid & 7;
        float* cp = Cs + c * ROWS + g * BLKW;
        float X[8][8];
        #pragma unroll
        for (int r = 0; r < 8; r++) {
            float4 a = *(const float4*)(cp + r * 8);
            float4 b = *(const float4*)(cp + r * 8 + 4);
            X[r][0] = a.x; X[r][1] = a.y; X[r][2] = a.z; X[r][3] = a.w;
            X[r][4] = b.x; X[r][5] = b.y; X[r][6] = b.z; X[r][7] = b.w;
        }
        #pragma unroll
        for (int n = 0; n < 8; n++) {
            float t[8];
            #pragma unroll
            for (int l = 0; l < 8; l++) {
                float s = X[n][0] * DM[l][0];
                #pragma unroll
                for (int m = 1; m < 8; m++) s = fmaf(X[n][m], DM[l][m], s);
                t[l] = s;
            }
            #pragma unroll
            for (int l = 0; l < 8; l++) X[n][l] = t[l];
        }
        #pragma unroll
        for (int k = 0; k < 8; k++) {
            float t[8];
            #pragma unroll
            for (int l = 0; l < 8; l++) {
                float s = DM[k][0] * X[0][l];
                #pragma unroll
                for (int n = 1; n < 8; n++) s = fmaf(DM[k][n], X[n][l], s);
                t[l] = s;
            }
            *(float4*)(cp + k * 8)     = make_float4(t[0], t[1], t[2], t[3]);
            *(float4*)(cp + k * 8 + 4) = make_float4(t[4], t[5], t[6], t[7]);
        }
    }
    __syncthreads();

    {
        const int og = tid >> 6;
        const int o0 = og * 8;
        const int tg = tid & 63;
        const int cg = tg >> 3;
        const int tb2 = (tg & 7) * 8;
        const float* crow0 = Cs + cg * BLKW + tb2;

        ull acc[4][8];
        {
            double2 b0 = *(const double2*)(bs + o0);
            double2 b1 = *(const double2*)(bs + o0 + 4);
            ull bp[4] = { d2l(b0.x), d2l(b0.y), d2l(b1.x), d2l(b1.y) };
            #pragma unroll
            for (int p = 0; p < 4; p++)
                #pragma unroll
                for (int t = 0; t < 8; t++) acc[p][t] = bp[p];
        }
        #pragma unroll 2
        for (int i = 0; i < 64; i++) {
            const float* cr = crow0 + i * ROWS;
            float4 ca = *(const float4*)(cr);
            float4 cb4 = *(const float4*)(cr + 4);
            float4 cc = *(const float4*)(cr + 8);
            float cv[12] = { ca.x, ca.y, ca.z, ca.w, cb4.x, cb4.y, cb4.z, cb4.w,
                             cc.x, cc.y, cc.z, cc.w };
            const float* wr = Ws + (i * 3) * WST + o0;
            double2 wA0 = *(const double2*)(wr);
            double2 wA1 = *(const double2*)(wr + 4);
            double2 wB0 = *(const double2*)(wr + WST);
            double2 wB1 = *(const double2*)(wr + WST + 4);
            double2 wC0 = *(const double2*)(wr + 2 * WST);
            double2 wC1 = *(const double2*)(wr + 2 * WST + 4);
            ull w0p[4] = { d2l(wA0.x), d2l(wA0.y), d2l(wA1.x), d2l(wA1.y) };
            ull w1p[4] = { d2l(wB0.x), d2l(wB0.y), d2l(wB1.x), d2l(wB1.y) };
            ull w2p[4] = { d2l(wC0.x), d2l(wC0.y), d2l(wC1.x), d2l(wC1.y) };
            ull dd0 = dup2(cv[0]);
            ull dd1 = dup2(cv[1]);
            ull dd2 = dup2(cv[2]);
            #pragma unroll
            for (int t = 0; t < 8; t++) {
                #pragma unroll
                for (int p = 0; p < 4; p++) {
                    acc[p][t] = ffma2(w0p[p], dd0, acc[p][t]);
                    acc[p][t] = ffma2(w1p[p], dd1, acc[p][t]);
                    acc[p][t] = ffma2(w2p[p], dd2, acc[p][t]);
                }
                dd0 = dd1; dd1 = dd2;
                if (t < 7) dd2 = dup2(cv[t + 3]);
            }
        }
        __syncthreads();
        float* orow = Cs + cg * BLKW + tb2;
        #pragma unroll
        for (int p = 0; p < 4; p++) {
            float lo[8], hi[8];
            #pragma unroll
            for (int t = 0; t < 8; t++) unpack2(acc[p][t], lo[t], hi[t]);
            float* r0 = orow + (size_t)(o0 + 2 * p) * ROWS;
            float* r1 = orow + (size_t)(o0 + 2 * p + 1) * ROWS;
            *(float4*)(r0)     = make_float4(lo[0], lo[1], lo[2], lo[3]);
            *(float4*)(r0 + 4) = make_float4(lo[4], lo[5], lo[6], lo[7]);
            *(float4*)(r1)     = make_float4(hi[0], hi[1], hi[2], hi[3]);
            *(float4*)(r1 + 4) = make_float4(hi[4], hi[5], hi[6], hi[7]);
        }
    }
    __syncthreads();

    {
        const int o = tid >> 3, g = tid & 7;
        const float* op = Cs + o * ROWS + g * BLKW;
        float Y[8][8];
        #pragma unroll
        for (int k = 0; k < 8; k++) {
            float4 a = *(const float4*)(op + k * 8);
            float4 b = *(const float4*)(op + k * 8 + 4);
            Y[k][0] = a.x; Y[k][1] = a.y; Y[k][2] = a.z; Y[k][3] = a.w;
            Y[k][4] = b.x; Y[k][5] = b.y; Y[k][6] = b.z; Y[k][7] = b.w;
        }
        #pragma unroll
        for (int k = 0; k < 8; k++) {
            float t[8];
            #pragma unroll
            for (int m = 0; m < 8; m++) {
                float s = Y[k][0] * DM[0][m];
                #pragma unroll
                for (int l = 1; l < 8; l++) s = fmaf(Y[k][l], DM[l][m], s);
                t[m] = s;
            }
            #pragma unroll
            for (int m = 0; m < 8; m++) Y[k][m] = t[m];
        }
        float* ob = out + ((size_t)bimg * 64 + o) * 65536 + (size_t)(bh * 8) * 256 + bwg * 64 + g * 8;
        #pragma unroll
        for (int n = 0; n < 8; n++) {
            float t[8];
            #pragma unroll
            for (int m = 0; m < 8; m++) {
                float s = DM[0][n] * Y[0][m];
                #pragma unroll
                for (int k = 1; k < 8; k++) s = fmaf(DM[k][n], Y[k][m], s);
                t[m] = s;
            }
            *(float4*)(ob + n * 256)     = make_float4(t[0], t[1], t[2], t[3]);
            *(float4*)(ob + n * 256 + 4) = make_float4(t[4], t[5], t[6], t[7]);
        }
    }
#endif
}

extern "C" void kernel_launch(void* const* d_in, const int* in_sizes, int n_in,
                              void* d_out, int out_size)
{
    (void)in_sizes; (void)n_in; (void)out_size;
    const float* x  = (const float*)d_in[0];
    const float* cw = (const float*)d_in[1];
    const float* cb = (const float*)d_in[2];
    float* out = (float*)d_out;

    cudaFuncSetAttribute(dct_tc_kernel,
                         cudaFuncAttributeMaxDynamicSharedMemorySize, SMEM_LAUNCH);
    dct_tc_kernel<<<1024, NT, SMEM_LAUNCH>>>(x, cw, cb, out);
}